// round 8
// baseline (speedup 1.0000x reference)
#include <cuda_runtime.h>

#define BATCH 4096
#define N_AG  32
#define F_IN  256
#define F_OUT 128

// Scratch (device-global: no allocation allowed)
__device__ float  g_means[BATCH * F_IN];          // 4 MiB
__device__ float4 g_wq[(F_IN / 4) * F_OUT];       // Wc quad-interleaved, 128 KB
__device__ float  g_c[F_OUT];                     // folded bias

// ---------- packed f32x2 helpers (SASS FFMA2 path, PTX-only) ----------
__device__ __forceinline__ unsigned long long fma2(unsigned long long a,
                                                   unsigned long long b,
                                                   unsigned long long c) {
    unsigned long long d;
    asm("fma.rn.f32x2 %0, %1, %2, %3;" : "=l"(d) : "l"(a), "l"(b), "l"(c));
    return d;
}
__device__ __forceinline__ float2 unpack2(unsigned long long v) {
    float2 f;
    asm("mov.b64 {%0, %1}, %2;" : "=f"(f.x), "=f"(f.y) : "l"(v));
    return f;
}

// ================= K0: fold Wc = lin_w @ out_w (quad layout), c = b1@W2+b2 ==
// grid 65 x 128 threads. Blocks 0..63: Wc rows {4b..4b+3} -> g_wq[b][j].
// Block 64: folded bias c.
__global__ __launch_bounds__(128) void k0_fold(
    const float* __restrict__ lin_w,   // [F_IN, F_OUT]
    const float* __restrict__ hgcn_b,  // [F_OUT]
    const float* __restrict__ out_w,   // [F_OUT, F_OUT]
    const float* __restrict__ out_b)   // [F_OUT]
{
    __shared__ float s[4][F_OUT];
    const int t = threadIdx.x;
    const int b = blockIdx.x;

    if (b < F_IN / 4) {
        #pragma unroll
        for (int r = 0; r < 4; ++r)
            s[r][t] = lin_w[(size_t)(4 * b + r) * F_OUT + t];
        __syncthreads();
        float a0 = 0.f, a1 = 0.f, a2 = 0.f, a3 = 0.f;
        #pragma unroll 8
        for (int k = 0; k < F_OUT; ++k) {
            float w = out_w[k * F_OUT + t];     // coalesced, L2
            a0 += s[0][k] * w;
            a1 += s[1][k] * w;
            a2 += s[2][k] * w;
            a3 += s[3][k] * w;
        }
        float4 r; r.x = a0; r.y = a1; r.z = a2; r.w = a3;
        g_wq[b * F_OUT + t] = r;
    } else {
        s[0][t] = hgcn_b[t];
        __syncthreads();
        float a = 0.f;
        #pragma unroll 8
        for (int k = 0; k < F_OUT; ++k)
            a += s[0][k] * out_w[k * F_OUT + t];
        g_c[t] = a + out_b[t];
    }
}

// ================= K1: mean over agents (measured 26us @ 67.5% DRAM) ========
// UNCHANGED — protect the measured-good kernel.
__global__ __launch_bounds__(256) void k1_mean(const float* __restrict__ in)
{
    const int t  = threadIdx.x;
    const int f4 = t & 63;
    const int bi = t >> 6;
    const int b  = blockIdx.x * 4 + bi;

    const float4* p = (const float4*)(in + (size_t)b * N_AG * F_IN) + f4;
    float4 a0 = {0,0,0,0}, a1 = {0,0,0,0}, a2 = {0,0,0,0}, a3 = {0,0,0,0};
    #pragma unroll
    for (int a = 0; a < N_AG; a += 4) {
        float4 v0 = p[(a + 0) * (F_IN / 4)];
        float4 v1 = p[(a + 1) * (F_IN / 4)];
        float4 v2 = p[(a + 2) * (F_IN / 4)];
        float4 v3 = p[(a + 3) * (F_IN / 4)];
        a0.x += v0.x; a0.y += v0.y; a0.z += v0.z; a0.w += v0.w;
        a1.x += v1.x; a1.y += v1.y; a1.z += v1.z; a1.w += v1.w;
        a2.x += v2.x; a2.y += v2.y; a2.z += v2.z; a2.w += v2.w;
        a3.x += v3.x; a3.y += v3.y; a3.z += v3.z; a3.w += v3.w;
    }
    float4 r;
    r.x = ((a0.x + a1.x) + (a2.x + a3.x)) * (1.0f / N_AG);
    r.y = ((a0.y + a1.y) + (a2.y + a3.y)) * (1.0f / N_AG);
    r.z = ((a0.z + a1.z) + (a2.z + a3.z)) * (1.0f / N_AG);
    r.w = ((a0.w + a1.w) + (a2.w + a3.w)) * (1.0f / N_AG);
    ((float4*)g_means)[(size_t)b * (F_IN / 4) + f4] = r;
}

// ================= K23: z = relu(m @ Wc + c) fused with broadcast ===========
// grid 1024 x 256 threads; TB=4 batch rows per block.
// Inner loop per 4 k-values: 1 LDG.128 (weights) + 2 LDS.128 (means) + 4 fma2.
#define TB 4
__global__ __launch_bounds__(256) void k23_mlp_bcast(float* __restrict__ out)
{
    __shared__ float sm[TB][F_IN];     // 4 KB mean rows
    __shared__ float sz[TB][F_OUT];    // 2 KB final z

    const int t  = threadIdx.x;
    const int B0 = blockIdx.x * TB;

    // ---- load mean tile: 256 float4, 1 per thread, coalesced ----
    ((float4*)sm)[t] = ((const float4*)(g_means + (size_t)B0 * F_IN))[t];
    __syncthreads();

    const int j  = t & (F_OUT - 1);    // column 0..127
    const int r0 = (t >> 7) * 2;       // rows r0, r0+1 (warp-uniform)

    unsigned long long acc0 = 0ull, acc1 = 0ull;

    #pragma unroll 8
    for (int q = 0; q < F_IN / 4; ++q) {
        // 4 consecutive k weights for column j: one LDG.128 (L1-resident for
        // the duplicate row-group; 128 consecutive float4 per warp-pair)
        ulonglong2 wv = *(const ulonglong2*)&g_wq[q * F_OUT + j];
        // mean quads: warp-uniform broadcast LDS.128
        ulonglong2 m0 = *(const ulonglong2*)&sm[r0 + 0][4 * q];
        ulonglong2 m1 = *(const ulonglong2*)&sm[r0 + 1][4 * q];
        acc0 = fma2(m0.x, wv.x, acc0);
        acc0 = fma2(m0.y, wv.y, acc0);
        acc1 = fma2(m1.x, wv.x, acc1);
        acc1 = fma2(m1.y, wv.y, acc1);
    }

    const float cj = g_c[j];
    float2 p0 = unpack2(acc0);
    float2 p1 = unpack2(acc1);
    float v0 = p0.x + p0.y + cj;
    float v1 = p1.x + p1.y + cj;
    sz[r0 + 0][j] = v0 > 0.f ? v0 : 0.f;
    sz[r0 + 1][j] = v1 > 0.f ? v1 : 0.f;
    __syncthreads();

    // ---- broadcast: block's output region is contiguous 4096 float4 ----
    float4* out4 = (float4*)out + (size_t)B0 * N_AG * (F_OUT / 4);
    const float4* z4 = (const float4*)sz;       // [TB][32]
    #pragma unroll
    for (int i = 0; i < TB * N_AG * (F_OUT / 4) / 256; ++i) {
        int o  = t + i * 256;
        int b  = o >> 10;       // / (N_AG * F_OUT/4)
        int f4 = o & 31;
        out4[o] = z4[b * 32 + f4];
    }
}

extern "C" void kernel_launch(void* const* d_in, const int* in_sizes, int n_in,
                              void* d_out, int out_size) {
    const float* in     = (const float*)d_in[0];
    const float* lin_w  = (const float*)d_in[1];
    const float* hgcn_b = (const float*)d_in[2];
    const float* out_w  = (const float*)d_in[3];
    const float* out_b  = (const float*)d_in[4];
    // d_in[5], d_in[6]: dense incidence indices, analytically folded.
    float* out = (float*)d_out;

    k0_fold      <<<F_IN / 4 + 1, 128>>>(lin_w, hgcn_b, out_w, out_b);
    k1_mean      <<<BATCH / 4,    256>>>(in);
    k23_mlp_bcast<<<BATCH / TB,   256>>>(out);
}

// round 9
// speedup vs baseline: 1.1717x; 1.1717x over previous
#include <cuda_runtime.h>

#define BATCH 4096
#define N_AG  32
#define F_IN  256
#define F_OUT 128

// Scratch (device-global: no allocation allowed)
__device__ float  g_means[BATCH * F_IN];          // 4 MiB
__device__ float4 g_wq[(F_IN / 4) * F_OUT];       // Wc quad-interleaved, 128 KB
__device__ float  g_c[F_OUT];                     // folded bias

#define FOLD_BLOCKS (F_IN / 4 + 1)                // 65

// ---------- packed f32x2 helpers (SASS FFMA2 path, PTX-only) ----------
__device__ __forceinline__ unsigned long long fma2(unsigned long long a,
                                                   unsigned long long b,
                                                   unsigned long long c) {
    unsigned long long d;
    asm("fma.rn.f32x2 %0, %1, %2, %3;" : "=l"(d) : "l"(a), "l"(b), "l"(c));
    return d;
}
__device__ __forceinline__ float2 unpack2(unsigned long long v) {
    float2 f;
    asm("mov.b64 {%0, %1}, %2;" : "=f"(f.x), "=f"(f.y) : "l"(v));
    return f;
}

// ================= kA: weight-fold (blocks 0..64) + mean (blocks 65..1088) ==
// Fold blocks scheduled first -> their L2-latency chains hide under the
// 26us DRAM-bound mean wave.
__global__ __launch_bounds__(256) void kA_fold_mean(
    const float* __restrict__ in,      // [BATCH, N_AG, F_IN]
    const float* __restrict__ lin_w,   // [F_IN, F_OUT]
    const float* __restrict__ hgcn_b,  // [F_OUT]
    const float* __restrict__ out_w,   // [F_OUT, F_OUT]
    const float* __restrict__ out_b)   // [F_OUT]
{
    const int t = threadIdx.x;

    if (blockIdx.x < FOLD_BLOCKS) {
        // ---- fold: Wc = lin_w @ out_w (quad layout), c = b1 @ W2 + b2 ----
        // 256 threads: j = t&127, k-half = t>>7; halve the latency chain,
        // reduce the two halves through smem.
        __shared__ float s[4][F_OUT];          // lin_w rows (or bias)
        __shared__ float part[2][4][F_OUT];    // per-half partial sums
        const int b  = blockIdx.x;
        const int j  = t & 127;
        const int h  = t >> 7;                 // k-half 0/1
        const int k0 = h * (F_OUT / 2);

        if (b < F_IN / 4) {
            if (h == 0) {
                #pragma unroll
                for (int r = 0; r < 4; ++r)
                    s[r][j] = lin_w[(size_t)(4 * b + r) * F_OUT + j];
            }
            __syncthreads();
            float a0 = 0.f, a1 = 0.f, a2 = 0.f, a3 = 0.f;
            #pragma unroll 8
            for (int k = k0; k < k0 + F_OUT / 2; ++k) {
                float w = out_w[k * F_OUT + j];     // coalesced, L2
                a0 += s[0][k] * w;
                a1 += s[1][k] * w;
                a2 += s[2][k] * w;
                a3 += s[3][k] * w;
            }
            part[h][0][j] = a0; part[h][1][j] = a1;
            part[h][2][j] = a2; part[h][3][j] = a3;
            __syncthreads();
            if (h == 0) {
                float4 r;
                r.x = part[0][0][j] + part[1][0][j];
                r.y = part[0][1][j] + part[1][1][j];
                r.z = part[0][2][j] + part[1][2][j];
                r.w = part[0][3][j] + part[1][3][j];
                g_wq[b * F_OUT + j] = r;
            }
        } else {
            if (h == 0) s[0][j] = hgcn_b[j];
            __syncthreads();
            float a = 0.f;
            #pragma unroll 8
            for (int k = k0; k < k0 + F_OUT / 2; ++k)
                a += s[0][k] * out_w[k * F_OUT + j];
            part[h][0][j] = a;
            __syncthreads();
            if (h == 0)
                g_c[j] = part[0][0][j] + part[1][0][j] + out_b[j];
        }
        return;
    }

    // ---- mean over agents: identical pattern to measured-good k1 ----
    const int blk = blockIdx.x - FOLD_BLOCKS;
    const int f4  = t & 63;
    const int bi  = t >> 6;
    const int b   = blk * 4 + bi;

    const float4* p = (const float4*)(in + (size_t)b * N_AG * F_IN) + f4;
    float4 a0 = {0,0,0,0}, a1 = {0,0,0,0}, a2 = {0,0,0,0}, a3 = {0,0,0,0};
    #pragma unroll
    for (int a = 0; a < N_AG; a += 4) {
        float4 v0 = p[(a + 0) * (F_IN / 4)];
        float4 v1 = p[(a + 1) * (F_IN / 4)];
        float4 v2 = p[(a + 2) * (F_IN / 4)];
        float4 v3 = p[(a + 3) * (F_IN / 4)];
        a0.x += v0.x; a0.y += v0.y; a0.z += v0.z; a0.w += v0.w;
        a1.x += v1.x; a1.y += v1.y; a1.z += v1.z; a1.w += v1.w;
        a2.x += v2.x; a2.y += v2.y; a2.z += v2.z; a2.w += v2.w;
        a3.x += v3.x; a3.y += v3.y; a3.z += v3.z; a3.w += v3.w;
    }
    float4 r;
    r.x = ((a0.x + a1.x) + (a2.x + a3.x)) * (1.0f / N_AG);
    r.y = ((a0.y + a1.y) + (a2.y + a3.y)) * (1.0f / N_AG);
    r.z = ((a0.z + a1.z) + (a2.z + a3.z)) * (1.0f / N_AG);
    r.w = ((a0.w + a1.w) + (a2.w + a3.w)) * (1.0f / N_AG);
    ((float4*)g_means)[(size_t)b * (F_IN / 4) + f4] = r;
}

// ================= kB: z = relu(m @ Wc + c) fused with broadcast ============
// grid 512 x 256 threads; TB=8 batch rows per block; 4 rows/thread.
// Inner loop per 4 k-values: 1 LDG.128 (weights) + 4 LDS.128 (means) + 8 fma2.
#define TB 8
__global__ __launch_bounds__(256) void kB_mlp_bcast(float* __restrict__ out)
{
    __shared__ float sm[TB][F_IN];     // 8 KB mean rows
    __shared__ float sz[TB][F_OUT];    // 4 KB final z

    const int t  = threadIdx.x;
    const int B0 = blockIdx.x * TB;

    // ---- load mean tile: 512 float4, 2 per thread, coalesced ----
    {
        const float4* gm4 = (const float4*)(g_means + (size_t)B0 * F_IN);
        float4* sm4 = (float4*)sm;
        sm4[t]       = gm4[t];
        sm4[t + 256] = gm4[t + 256];
    }
    __syncthreads();

    const int j  = t & (F_OUT - 1);    // column 0..127
    const int r0 = (t >> 7) * 4;       // rows r0..r0+3 (warp-uniform)

    unsigned long long acc0 = 0ull, acc1 = 0ull, acc2 = 0ull, acc3 = 0ull;

    #pragma unroll 8
    for (int q = 0; q < F_IN / 4; ++q) {
        ulonglong2 wv = *(const ulonglong2*)&g_wq[q * F_OUT + j];  // LDG.128
        ulonglong2 m0 = *(const ulonglong2*)&sm[r0 + 0][4 * q];    // bcast LDS
        ulonglong2 m1 = *(const ulonglong2*)&sm[r0 + 1][4 * q];
        ulonglong2 m2 = *(const ulonglong2*)&sm[r0 + 2][4 * q];
        ulonglong2 m3 = *(const ulonglong2*)&sm[r0 + 3][4 * q];
        acc0 = fma2(m0.x, wv.x, acc0);
        acc0 = fma2(m0.y, wv.y, acc0);
        acc1 = fma2(m1.x, wv.x, acc1);
        acc1 = fma2(m1.y, wv.y, acc1);
        acc2 = fma2(m2.x, wv.x, acc2);
        acc2 = fma2(m2.y, wv.y, acc2);
        acc3 = fma2(m3.x, wv.x, acc3);
        acc3 = fma2(m3.y, wv.y, acc3);
    }

    const float cj = g_c[j];
    {
        float2 p0 = unpack2(acc0), p1 = unpack2(acc1);
        float2 p2 = unpack2(acc2), p3 = unpack2(acc3);
        float v0 = p0.x + p0.y + cj;
        float v1 = p1.x + p1.y + cj;
        float v2 = p2.x + p2.y + cj;
        float v3 = p3.x + p3.y + cj;
        sz[r0 + 0][j] = v0 > 0.f ? v0 : 0.f;
        sz[r0 + 1][j] = v1 > 0.f ? v1 : 0.f;
        sz[r0 + 2][j] = v2 > 0.f ? v2 : 0.f;
        sz[r0 + 3][j] = v3 > 0.f ? v3 : 0.f;
    }
    __syncthreads();

    // ---- broadcast: block's output region is contiguous 8192 float4 ----
    float4* out4 = (float4*)out + (size_t)B0 * N_AG * (F_OUT / 4);
    const float4* z4 = (const float4*)sz;       // [TB][32]
    #pragma unroll
    for (int i = 0; i < TB * N_AG * (F_OUT / 4) / 256; ++i) {
        int o  = t + i * 256;
        int b  = o >> 10;       // / (N_AG * F_OUT/4)
        int f4 = o & 31;
        out4[o] = z4[b * 32 + f4];
    }
}

extern "C" void kernel_launch(void* const* d_in, const int* in_sizes, int n_in,
                              void* d_out, int out_size) {
    const float* in     = (const float*)d_in[0];
    const float* lin_w  = (const float*)d_in[1];
    const float* hgcn_b = (const float*)d_in[2];
    const float* out_w  = (const float*)d_in[3];
    const float* out_b  = (const float*)d_in[4];
    // d_in[5], d_in[6]: dense incidence indices, analytically folded.
    float* out = (float*)d_out;

    kA_fold_mean<<<BATCH / 4 + FOLD_BLOCKS, 256>>>(in, lin_w, hgcn_b,
                                                   out_w, out_b);
    kB_mlp_bcast<<<BATCH / TB, 256>>>(out);
}